// round 4
// baseline (speedup 1.0000x reference)
#include <cuda_runtime.h>

// Problem constants (fixed by the reference module)
#define N_  16
#define D_  3
#define H_  160
#define W_  160
#define M_  8
#define K_  10
#define P_  15
#define PM_ 7               // (P-1)/2
#define OH_ (H_ - P_ + 1)   // 146
#define OW_ (W_ - P_ + 1)   // 146
#define MK_ (M_ * K_)       // 80
#define PLANE_ (OH_ * OW_)  // 21316

// Strip layout: 32 cols x 49 rows per warp.
// 5 column bands x 3 row groups = 15 strips per (n,mk) plane.
// Total strips = 1280 * 15 = 19200 warps = 2400 blocks of 8 warps.
// 2400 / (148 SMs * 8 blocks/SM) ~= 2.03 waves (near-integer by design).
#define CB_  5
#define RG_  3
#define ROWS_PER_STRIP_ 49          // last group covers 48
#define STRIPS_PER_PLANE_ (CB_ * RG_)   // 15
#define TOTAL_STRIPS_ (N_ * MK_ * STRIPS_PER_PLANE_)  // 19200
#define WARPS_PER_BLOCK_ 8
#define NBLOCKS_ (TOTAL_STRIPS_ / WARPS_PER_BLOCK_)   // 2400

__global__ __launch_bounds__(WARPS_PER_BLOCK_ * 32)
void fern_bits_kernel(
    const float* __restrict__ T,
    const float* __restrict__ dx1, const float* __restrict__ dx2,
    const float* __restrict__ dy1, const float* __restrict__ dy2,
    const float* __restrict__ th,  const float* __restrict__ amb,
    const int*   __restrict__ channels,
    float* __restrict__ out)
{
    // ---- strip decode (once per warp) ----
    const int sid = blockIdx.x * WARPS_PER_BLOCK_ + (threadIdx.x >> 5);
    const int nmk = sid / STRIPS_PER_PLANE_;
    const int rem = sid - nmk * STRIPS_PER_PLANE_;
    const int cb  = rem % CB_;
    const int rg  = rem / CB_;

    const int n   = nmk / MK_;
    const int mk  = nmk - n * MK_;
    const int m   = mk / K_;
    const int k   = mk - m * K_;
    const int ch  = channels[k];

    // ---- per-(m,k) parameters (uniform per warp, broadcast loads) ----
    const float a1x = dx1[mk], a2x = dx2[mk];
    const float a1y = dy1[mk], a2y = dy2[mk];
    const float fl1x = floorf(a1x), fl2x = floorf(a2x);
    const float fl1y = floorf(a1y), fl2y = floorf(a2y);
    const float f1x = a1x - fl1x, f2x = a2x - fl2x;
    const float f1y = a1y - fl1y, f2y = a2y - fl2y;
    const float g1x = 1.0f - f1x, g2x = 1.0f - f2x;
    const float g1y = 1.0f - f1y;
    const float ng2y = -(1.0f - f2y), nf2y = -f2y;
    const int sx1 = PM_ + (int)fl1x, sx2 = PM_ + (int)fl2x;
    const int sy1 = PM_ + (int)fl1y, sy2 = PM_ + (int)fl2y;

    const float thv = th[mk];
    const float pos = amb[(m * 2 + 0) * K_ + k];
    const float neg = amb[(m * 2 + 1) * K_ + k];
    const float inv = 1.0f / (pos - neg + 1e-29f);
    const float c   = -(thv + neg) * inv;   // v = sat(temp*inv + c)

    // ---- lane geometry ----
    const int lane = threadIdx.x & 31;
    const int x    = cb * 32 + lane;
    const int xc   = min(x, OW_ - 1);       // clamp loads; store predicated
    const bool valid = (x < OW_);
    const int y0   = rg * ROWS_PER_STRIP_;
    const int hv   = min(ROWS_PER_STRIP_, OH_ - y0);   // 49,49,48

    // In-bounds: sy,sx in [0,12]; max row = 12+97+49 = 158 < 160,
    // max col = 12+145+1 = 158 < 160. No padding needed.
    const float* __restrict__ img = T + ((size_t)(n * D_ + ch)) * (H_ * W_);
    const float* p1 = img + (sy1 + y0) * W_ + sx1 + xc;
    const float* p2 = img + (sy2 + y0) * W_ + sx2 + xc;
    float* op = out + (size_t)nmk * PLANE_ + y0 * OW_ + x;

    // ---- prologue: horizontal lerp of input row 0 of the strip ----
    float prev1, prev2;
    {
        const float a0 = __ldg(p1), a1 = __ldg(p1 + 1);
        const float b0 = __ldg(p2), b1 = __ldg(p2 + 1);
        prev1 = g1x * a0 + f1x * a1;
        prev2 = g2x * b0 + f2x * b1;
    }

    // ---- rolling mainloop: one output row per iteration ----
    #pragma unroll 4
    for (int r = 1; r <= hv; r++) {
        const float a0 = __ldg(p1 + r * W_), a1 = __ldg(p1 + r * W_ + 1);
        const float b0 = __ldg(p2 + r * W_), b1 = __ldg(p2 + r * W_ + 1);
        const float cur1 = g1x * a0 + f1x * a1;
        const float cur2 = g2x * b0 + f2x * b1;

        float temp = g1y * prev1;
        temp = fmaf(f1y,  cur1,  temp);
        temp = fmaf(ng2y, prev2, temp);
        temp = fmaf(nf2y, cur2,  temp);
        prev1 = cur1;
        prev2 = cur2;

        if (fabsf(temp) < 1e-5f) temp = 0.0f;
        const float v = __saturatef(fmaf(temp, inv, c));
        if (valid) op[(r - 1) * OW_] = v;
    }
}

extern "C" void kernel_launch(void* const* d_in, const int* in_sizes, int n_in,
                              void* d_out, int out_size)
{
    const float* T        = (const float*)d_in[0];
    const float* dx1      = (const float*)d_in[1];
    const float* dx2      = (const float*)d_in[2];
    const float* dy1      = (const float*)d_in[3];
    const float* dy2      = (const float*)d_in[4];
    const float* th       = (const float*)d_in[5];
    const float* amb      = (const float*)d_in[6];
    const int*   channels = (const int*)  d_in[7];
    float* out = (float*)d_out;

    fern_bits_kernel<<<NBLOCKS_, WARPS_PER_BLOCK_ * 32>>>(
        T, dx1, dx2, dy1, dy2, th, amb, channels, out);
}

// round 5
// speedup vs baseline: 1.8290x; 1.8290x over previous
#include <cuda_runtime.h>

// Problem constants (fixed by the reference module)
#define N_  16
#define D_  3
#define H_  160
#define W_  160
#define M_  8
#define K_  10
#define P_  15
#define PM_ 7               // (P-1)/2
#define OH_ (H_ - P_ + 1)   // 146
#define OW_ (W_ - P_ + 1)   // 146
#define MK_ (M_ * K_)       // 80
#define PLANE_ (OH_ * OW_)  // 21316

// Strip: 32 cols x 16 rows per warp, fully unrolled, no predication.
// 5 column bands (last clamped to x0=114) x 10 row groups (last clamped
// to y0=130): overlapped regions are written twice with identical values.
#define HTILE_ 16
#define CB_    5
#define RG_    10
#define STRIPS_PER_PLANE_ (CB_ * RG_)                  // 50
#define TOTAL_STRIPS_ (N_ * MK_ * STRIPS_PER_PLANE_)   // 64000
#define WARPS_PER_BLOCK_ 8
#define NBLOCKS_ (TOTAL_STRIPS_ / WARPS_PER_BLOCK_)    // 8000

__global__ __launch_bounds__(WARPS_PER_BLOCK_ * 32)
void fern_bits_kernel(
    const float* __restrict__ T,
    const float* __restrict__ dx1, const float* __restrict__ dx2,
    const float* __restrict__ dy1, const float* __restrict__ dy2,
    const float* __restrict__ th,  const float* __restrict__ amb,
    const int*   __restrict__ channels,
    float* __restrict__ out)
{
    // ---- strip decode ----
    const int sid = blockIdx.x * WARPS_PER_BLOCK_ + (threadIdx.x >> 5);
    const int nmk = sid / STRIPS_PER_PLANE_;
    const int rem = sid - nmk * STRIPS_PER_PLANE_;
    const int cb  = rem % CB_;
    const int rg  = rem / CB_;

    const int n   = nmk / MK_;
    const int mk  = nmk - n * MK_;
    const int m   = mk / K_;
    const int k   = mk - m * K_;
    const int ch  = channels[k];

    // ---- per-(m,k) parameters (uniform per warp, broadcast loads) ----
    const float a1x = dx1[mk], a2x = dx2[mk];
    const float a1y = dy1[mk], a2y = dy2[mk];
    const float fl1x = floorf(a1x), fl2x = floorf(a2x);
    const float fl1y = floorf(a1y), fl2y = floorf(a2y);
    const float f1x = a1x - fl1x, f2x = a2x - fl2x;
    const float f1y = a1y - fl1y, f2y = a2y - fl2y;
    const float g1x = 1.0f - f1x, g2x = 1.0f - f2x;
    const float g1y  = 1.0f - f1y;
    const float ng2y = -(1.0f - f2y), nf2y = -f2y;
    const int sx1 = PM_ + (int)fl1x, sx2 = PM_ + (int)fl2x;
    const int sy1 = PM_ + (int)fl1y, sy2 = PM_ + (int)fl2y;

    const float thv = th[mk];
    const float pos = amb[(m * 2 + 0) * K_ + k];
    const float neg = amb[(m * 2 + 1) * K_ + k];
    const float inv = 1.0f / (pos - neg + 1e-29f);
    const float c   = -(thv + neg) * inv;   // v = sat(temp*inv + c)

    // ---- lane geometry (no predication: tail strips overlap) ----
    const int lane = threadIdx.x & 31;
    const int x0   = min(cb * 32, OW_ - 32);     // 0,32,64,96,114
    const int y0   = min(rg * HTILE_, OH_ - HTILE_);  // 0..128, 130
    const int x    = x0 + lane;

    // In-bounds: sy,sx in [0,12]; max row = 12 + 130 + 16 = 158 < 160,
    // max col = 12 + 145 + 1 = 158 < 160. No padding needed.
    const float* __restrict__ img = T + ((size_t)(n * D_ + ch)) * (H_ * W_);
    const float* p1 = img + (sy1 + y0) * W_ + sx1 + x;
    const float* p2 = img + (sy2 + y0) * W_ + sx2 + x;
    float* op = out + (size_t)nmk * PLANE_ + y0 * OW_ + x;

    // ---- prologue: horizontal lerp of strip input row 0 ----
    float prev1, prev2;
    {
        const float a0 = __ldg(p1), a1 = __ldg(p1 + 1);
        const float b0 = __ldg(p2), b1 = __ldg(p2 + 1);
        prev1 = g1x * a0 + f1x * a1;
        prev2 = g2x * b0 + f2x * b1;
    }

    // ---- fully unrolled rolling mainloop: compile-time offsets ----
    #pragma unroll
    for (int r = 1; r <= HTILE_; r++) {
        const float a0 = __ldg(p1 + r * W_), a1 = __ldg(p1 + r * W_ + 1);
        const float b0 = __ldg(p2 + r * W_), b1 = __ldg(p2 + r * W_ + 1);
        const float cur1 = g1x * a0 + f1x * a1;
        const float cur2 = g2x * b0 + f2x * b1;

        float temp = g1y * prev1;
        temp = fmaf(f1y,  cur1,  temp);
        temp = fmaf(ng2y, prev2, temp);
        temp = fmaf(nf2y, cur2,  temp);
        prev1 = cur1;
        prev2 = cur2;

        if (fabsf(temp) < 1e-5f) temp = 0.0f;
        op[(r - 1) * OW_] = __saturatef(fmaf(temp, inv, c));
    }
}

extern "C" void kernel_launch(void* const* d_in, const int* in_sizes, int n_in,
                              void* d_out, int out_size)
{
    const float* T        = (const float*)d_in[0];
    const float* dx1      = (const float*)d_in[1];
    const float* dx2      = (const float*)d_in[2];
    const float* dy1      = (const float*)d_in[3];
    const float* dy2      = (const float*)d_in[4];
    const float* th       = (const float*)d_in[5];
    const float* amb      = (const float*)d_in[6];
    const int*   channels = (const int*)  d_in[7];
    float* out = (float*)d_out;

    fern_bits_kernel<<<NBLOCKS_, WARPS_PER_BLOCK_ * 32>>>(
        T, dx1, dx2, dy1, dy2, th, amb, channels, out);
}

// round 6
// speedup vs baseline: 1.8626x; 1.0184x over previous
#include <cuda_runtime.h>

// Problem constants (fixed by the reference module)
#define N_  16
#define D_  3
#define H_  160
#define W_  160
#define M_  8
#define K_  10
#define P_  15
#define PM_ 7               // (P-1)/2
#define OH_ (H_ - P_ + 1)   // 146
#define OW_ (W_ - P_ + 1)   // 146
#define MK_ (M_ * K_)       // 80
#define PLANE_ (OH_ * OW_)  // 21316

// Strip: 32 cols x 32 rows per warp, fully unrolled rolling vertical lerp,
// no predication. 5 column bands (last clamped to x0=114) x 5 row groups
// (last clamped to y0=114): overlapped regions write identical values.
#define HTILE_ 32
#define CB_    5
#define RG_    5
#define STRIPS_PER_PLANE_ (CB_ * RG_)                  // 25
#define TOTAL_STRIPS_ (N_ * MK_ * STRIPS_PER_PLANE_)   // 32000
#define WARPS_PER_BLOCK_ 8
#define NBLOCKS_ (TOTAL_STRIPS_ / WARPS_PER_BLOCK_)    // 4000

__global__ __launch_bounds__(WARPS_PER_BLOCK_ * 32)
void fern_bits_kernel(
    const float* __restrict__ T,
    const float* __restrict__ dx1, const float* __restrict__ dx2,
    const float* __restrict__ dy1, const float* __restrict__ dy2,
    const float* __restrict__ th,  const float* __restrict__ amb,
    const int*   __restrict__ channels,
    float* __restrict__ out)
{
    // ---- strip decode ----
    const int sid = blockIdx.x * WARPS_PER_BLOCK_ + (threadIdx.x >> 5);
    const int nmk = sid / STRIPS_PER_PLANE_;
    const int rem = sid - nmk * STRIPS_PER_PLANE_;
    const int cb  = rem % CB_;
    const int rg  = rem / CB_;

    const int n   = nmk / MK_;
    const int mk  = nmk - n * MK_;
    const int m   = mk / K_;
    const int k   = mk - m * K_;
    const int ch  = channels[k];

    // ---- per-(m,k) parameters (uniform per warp, broadcast loads) ----
    const float a1x = dx1[mk], a2x = dx2[mk];
    const float a1y = dy1[mk], a2y = dy2[mk];
    const float fl1x = floorf(a1x), fl2x = floorf(a2x);
    const float fl1y = floorf(a1y), fl2y = floorf(a2y);
    const float f1x = a1x - fl1x, f2x = a2x - fl2x;
    const float f1y = a1y - fl1y, f2y = a2y - fl2y;
    const float g1x = 1.0f - f1x, g2x = 1.0f - f2x;
    const float g1y  = 1.0f - f1y;
    const float ng2y = -(1.0f - f2y), nf2y = -f2y;
    const int sx1 = PM_ + (int)fl1x, sx2 = PM_ + (int)fl2x;
    const int sy1 = PM_ + (int)fl1y, sy2 = PM_ + (int)fl2y;

    const float thv = th[mk];
    const float pos = amb[(m * 2 + 0) * K_ + k];
    const float neg = amb[(m * 2 + 1) * K_ + k];
    const float inv = 1.0f / (pos - neg + 1e-29f);
    const float c   = -(thv + neg) * inv;   // v = sat(temp*inv + c)

    // ---- lane geometry (no predication: tail strips overlap) ----
    const int lane = threadIdx.x & 31;
    const int x0   = min(cb * 32, OW_ - 32);          // 0,32,64,96,114
    const int y0   = min(rg * HTILE_, OH_ - HTILE_);  // 0,32,64,96,114
    const int x    = x0 + lane;

    // In-bounds: sy,sx in [0,12]; max row = 12 + 114 + 32 = 158 < 160,
    // max col = 12 + 145 + 1 = 158 < 160. No padding needed.
    const float* __restrict__ img = T + ((size_t)(n * D_ + ch)) * (H_ * W_);
    const float* p1 = img + (sy1 + y0) * W_ + sx1 + x;
    const float* p2 = img + (sy2 + y0) * W_ + sx2 + x;
    float* op = out + (size_t)nmk * PLANE_ + y0 * OW_ + x;

    // ---- prologue: horizontal lerp of strip input row 0 ----
    float prev1, prev2;
    {
        const float a0 = __ldg(p1), a1 = __ldg(p1 + 1);
        const float b0 = __ldg(p2), b1 = __ldg(p2 + 1);
        prev1 = g1x * a0 + f1x * a1;
        prev2 = g2x * b0 + f2x * b1;
    }

    // ---- fully unrolled rolling mainloop: compile-time offsets ----
    #pragma unroll
    for (int r = 1; r <= HTILE_; r++) {
        const float a0 = __ldg(p1 + r * W_), a1 = __ldg(p1 + r * W_ + 1);
        const float b0 = __ldg(p2 + r * W_), b1 = __ldg(p2 + r * W_ + 1);
        const float cur1 = g1x * a0 + f1x * a1;
        const float cur2 = g2x * b0 + f2x * b1;

        float temp = g1y * prev1;
        temp = fmaf(f1y,  cur1,  temp);
        temp = fmaf(ng2y, prev2, temp);
        temp = fmaf(nf2y, cur2,  temp);
        prev1 = cur1;
        prev2 = cur2;

        if (fabsf(temp) < 1e-5f) temp = 0.0f;
        op[(r - 1) * OW_] = __saturatef(fmaf(temp, inv, c));
    }
}

extern "C" void kernel_launch(void* const* d_in, const int* in_sizes, int n_in,
                              void* d_out, int out_size)
{
    const float* T        = (const float*)d_in[0];
    const float* dx1      = (const float*)d_in[1];
    const float* dx2      = (const float*)d_in[2];
    const float* dy1      = (const float*)d_in[3];
    const float* dy2      = (const float*)d_in[4];
    const float* th       = (const float*)d_in[5];
    const float* amb      = (const float*)d_in[6];
    const int*   channels = (const int*)  d_in[7];
    float* out = (float*)d_out;

    fern_bits_kernel<<<NBLOCKS_, WARPS_PER_BLOCK_ * 32>>>(
        T, dx1, dx2, dy1, dy2, th, amb, channels, out);
}